// round 1
// baseline (speedup 1.0000x reference)
#include <cuda_runtime.h>

// Problem constants
#define NB    32      // batch
#define NHH   32      // H
#define NWW   32      // W
#define NCIN  256     // input channels
#define NCOUT 256     // output channels per group
#define NG    4       // groups
#define CING  64      // input channels per group
#define NCH   1024    // NG * NCOUT (BN channels)
#define HW    1024    // H*W
#define COC   8       // couts per conv block
#define PST   34      // padded plane row stride

// Device scratch (no allocations allowed)
__device__ float  g_alpha[NCOUT];
__device__ float  g_sgn[NCOUT * NCIN * 12];          // [co][ci][12], 9 used, float +-1
__device__ float  g_bconv[(size_t)NB * NCH * HW];    // 134 MB: [((b*G+g)*COUT+co)*HW + px]
__device__ double g_sum[NCH];
__device__ double g_sumsq[NCH];
__device__ float  g_cA[NCH];
__device__ float  g_cB[NCH];

// ---------------------------------------------------------------------------
// Kernel 0: per-cout alpha = mean|w|, sign extraction, stats zeroing
// grid: 256 blocks (one per cout), 256 threads
// ---------------------------------------------------------------------------
__global__ void prep_kernel(const float* __restrict__ w) {
    const int co = blockIdx.x;
    const int t  = threadIdx.x;

    // zero BN stats accumulators (1024 doubles each; 4 per block)
    if (t < 4) {
        g_sum[co * 4 + t]   = 0.0;
        g_sumsq[co * 4 + t] = 0.0;
    }

    const float* wc = w + (size_t)co * NCIN * 9;

    float s = 0.0f;
    for (int i = t; i < NCIN * 9; i += 256) s += fabsf(wc[i]);

    __shared__ float red[256];
    red[t] = s;
    __syncthreads();
    for (int o = 128; o > 0; o >>= 1) {
        if (t < o) red[t] += red[t + o];
        __syncthreads();
    }
    if (t == 0) g_alpha[co] = red[0] / 2304.0f;

    // signs: w >= 0 -> +1 else -1 (matches jnp.where(x >= 0, 1, -1))
    for (int i = t; i < NCIN * 9; i += 256) {
        int ci = i / 9;
        int k  = i % 9;
        g_sgn[(size_t)co * (NCIN * 12) + ci * 12 + k] = (wc[i] >= 0.0f) ? 1.0f : -1.0f;
    }
}

// ---------------------------------------------------------------------------
// Kernel 1: binary-weight grouped conv. Each block: (co_chunk of 8, g, b),
// full 32x32 plane, loop over 64 input channels. Fused per-channel
// sum / sumsq block reduction -> fp64 atomics.
// grid: (32, 4, 32), 256 threads. Thread owns 4 pixels of one row.
// ---------------------------------------------------------------------------
__global__ void __launch_bounds__(256) conv_kernel(const float* __restrict__ x) {
    const int t   = threadIdx.x;
    const int co0 = blockIdx.x * COC;   // 0..255 step 8
    const int g   = blockIdx.y;         // 0..3
    const int b   = blockIdx.z;         // 0..31

    __shared__ float sp[PST * PST];          // padded input plane (zeros on border)
    __shared__ float ss[COC * CING * 12];    // signs for this (co chunk, group): 24 KB
    __shared__ float red1[COC][8];
    __shared__ float red2[COC][8];

    // zero padded plane (border stays zero for SAME padding)
    for (int i = t; i < PST * PST; i += 256) sp[i] = 0.0f;

    // load signs: per co a contiguous 768-float slab
    for (int i = t; i < COC * CING * 12; i += 256) {
        int coi = i / (CING * 12);
        int rem = i - coi * (CING * 12);
        ss[i] = g_sgn[(size_t)(co0 + coi) * (NCIN * 12) + (size_t)g * (CING * 12) + rem];
    }

    float acc[COC][4];
#pragma unroll
    for (int a = 0; a < COC; a++)
#pragma unroll
        for (int p = 0; p < 4; p++) acc[a][p] = 0.0f;

    const int h  = t >> 3;          // 0..31
    const int w0 = (t & 7) * 4;     // 0,4,...,28
    const float* xb = x + ((size_t)b * NCIN + (size_t)g * CING) * HW;

    __syncthreads();

    for (int c = 0; c < CING; c++) {
        __syncthreads();   // previous iteration's reads done
        for (int i = t; i < HW; i += 256) {
            sp[(1 + (i >> 5)) * PST + 1 + (i & 31)] = xb[(size_t)c * HW + i];
        }
        __syncthreads();

        float r0[6], r1[6], r2[6];
#pragma unroll
        for (int i = 0; i < 6; i++) {
            r0[i] = sp[(h    ) * PST + w0 + i];
            r1[i] = sp[(h + 1) * PST + w0 + i];
            r2[i] = sp[(h + 2) * PST + w0 + i];
        }

        const float* scbase = ss + c * 12;
#pragma unroll
        for (int co = 0; co < COC; co++) {
            const float* sco = scbase + co * (CING * 12);
            const float4 sA = *reinterpret_cast<const float4*>(sco);
            const float4 sB = *reinterpret_cast<const float4*>(sco + 4);
            const float  s8 = sco[8];
#pragma unroll
            for (int p = 0; p < 4; p++) {
                // two-level accumulation: 9-tap partial, then one add
                float tv;
                tv = sA.x * r0[p];
                tv = fmaf(sA.y, r0[p + 1], tv);
                tv = fmaf(sA.z, r0[p + 2], tv);
                tv = fmaf(sA.w, r1[p],     tv);
                tv = fmaf(sB.x, r1[p + 1], tv);
                tv = fmaf(sB.y, r1[p + 2], tv);
                tv = fmaf(sB.z, r2[p],     tv);
                tv = fmaf(sB.w, r2[p + 1], tv);
                tv = fmaf(s8,   r2[p + 2], tv);
                acc[co][p] += tv;
            }
        }
    }

    // store bconv (float4, perfectly coalesced)
    const size_t outbase = (((size_t)b * NG + g) * NCOUT + co0) * HW + (size_t)h * NWW + w0;
#pragma unroll
    for (int co = 0; co < COC; co++) {
        float4 v = make_float4(acc[co][0], acc[co][1], acc[co][2], acc[co][3]);
        *reinterpret_cast<float4*>(&g_bconv[outbase + (size_t)co * HW]) = v;
    }

    // fused BN stats: block partials then fp64 atomics
    const int lane = t & 31;
    const int wid  = t >> 5;
#pragma unroll
    for (int co = 0; co < COC; co++) {
        float s1 = acc[co][0] + acc[co][1] + acc[co][2] + acc[co][3];
        float s2 = acc[co][0] * acc[co][0] + acc[co][1] * acc[co][1]
                 + acc[co][2] * acc[co][2] + acc[co][3] * acc[co][3];
#pragma unroll
        for (int o = 16; o > 0; o >>= 1) {
            s1 += __shfl_xor_sync(0xFFFFFFFFu, s1, o);
            s2 += __shfl_xor_sync(0xFFFFFFFFu, s2, o);
        }
        if (lane == 0) { red1[co][wid] = s1; red2[co][wid] = s2; }
    }
    __syncthreads();
    if (t < COC) {
        float s1 = 0.0f, s2 = 0.0f;
#pragma unroll
        for (int wdx = 0; wdx < 8; wdx++) { s1 += red1[t][wdx]; s2 += red2[t][wdx]; }
        const int ch = g * NCOUT + co0 + t;
        atomicAdd(&g_sum[ch],   (double)s1);
        atomicAdd(&g_sumsq[ch], (double)s2);
    }
}

// ---------------------------------------------------------------------------
// Kernel 2: finalize per-channel BN affine in fp64.
// y = psum*inv + (beta - mean*inv), psum = alpha*bconv
// -> sign test on bconv*cA + cB
// ---------------------------------------------------------------------------
__global__ void finalize_kernel(const float* __restrict__ gamma,
                                const float* __restrict__ beta) {
    const int ch = blockIdx.x * 256 + threadIdx.x;   // 0..1023
    if (ch >= NCH) return;
    const int co = ch & (NCOUT - 1);
    const double N = (double)NB * (double)HW;        // 32768
    const double mean_b = g_sum[ch] / N;
    const double var_b  = g_sumsq[ch] / N - mean_b * mean_b;
    const double a      = (double)g_alpha[co];
    const double var_p  = a * a * var_b;
    const double inv    = rsqrt(var_p + 1e-5) * (double)gamma[ch];
    g_cA[ch] = (float)(a * inv);
    g_cB[ch] = (float)((double)beta[ch] - a * mean_b * inv);
}

// ---------------------------------------------------------------------------
// Kernel 3: sign + group merge + qrelu quantization.
// y in {-4,-2,0,2,4} -> q in {0, 32/15, 4} (round-half-even on 7.5 -> 8)
// ---------------------------------------------------------------------------
__global__ void merge_kernel(float* __restrict__ out) {
    const size_t i   = (size_t)blockIdx.x * 256 + threadIdx.x;  // float4 index
    const size_t px4 = i & 255;           // HW/4 = 256 float4 per plane
    const size_t bc  = i >> 8;
    const size_t co  = bc & (NCOUT - 1);
    const size_t b   = bc >> 8;

    int y0 = 0, y1 = 0, y2 = 0, y3 = 0;
#pragma unroll
    for (int g = 0; g < NG; g++) {
        const size_t idx = (((b * NG + g) * NCOUT + co) * (HW / 4)) + px4;
        const float4 v = reinterpret_cast<const float4*>(g_bconv)[idx];
        const int ch = g * NCOUT + (int)co;
        const float cA = g_cA[ch];
        const float cB = g_cB[ch];
        y0 += (fmaf(v.x, cA, cB) >= 0.0f) ? 1 : -1;
        y1 += (fmaf(v.y, cA, cB) >= 0.0f) ? 1 : -1;
        y2 += (fmaf(v.z, cA, cB) >= 0.0f) ? 1 : -1;
        y3 += (fmaf(v.w, cA, cB) >= 0.0f) ? 1 : -1;
    }

    const float QMID = (8.0f / 15.0f) * 4.0f;   // 2.1333334
    float4 o;
    o.x = (y0 >= 4) ? 4.0f : ((y0 >= 2) ? QMID : 0.0f);
    o.y = (y1 >= 4) ? 4.0f : ((y1 >= 2) ? QMID : 0.0f);
    o.z = (y2 >= 4) ? 4.0f : ((y2 >= 2) ? QMID : 0.0f);
    o.w = (y3 >= 4) ? 4.0f : ((y3 >= 2) ? QMID : 0.0f);
    reinterpret_cast<float4*>(out)[i] = o;
}

// ---------------------------------------------------------------------------
extern "C" void kernel_launch(void* const* d_in, const int* in_sizes, int n_in,
                              void* d_out, int out_size) {
    (void)in_sizes; (void)n_in; (void)out_size;
    const float* x     = (const float*)d_in[0];
    const float* w     = (const float*)d_in[1];
    const float* gamma = (const float*)d_in[2];
    const float* beta  = (const float*)d_in[3];
    float* out = (float*)d_out;

    prep_kernel<<<256, 256>>>(w);
    dim3 gconv(NCOUT / COC, NG, NB);   // (32, 4, 32)
    conv_kernel<<<gconv, 256>>>(x);
    finalize_kernel<<<4, 256>>>(gamma, beta);
    merge_kernel<<<(NB * NCOUT * HW / 4) / 256, 256>>>(out);   // 8192 blocks
}